// round 2
// baseline (speedup 1.0000x reference)
#include <cuda_runtime.h>
#include <cuda_bf16.h>
#include <math.h>

#define BB    2304
#define CH    22
#define TP    250
#define ST    64
#define KW    13
#define RR    32
#define NFE   528

__device__ float g_z[(size_t)BB * ST * TP];
__device__ float g_y[(size_t)BB * RR * RR];

__device__ __forceinline__ unsigned long long pk2(float a, float b) {
    unsigned long long r;
    asm("mov.b64 %0, {%1, %2};" : "=l"(r)
        : "r"(__float_as_uint(a)), "r"(__float_as_uint(b)));
    return r;
}
__device__ __forceinline__ void upk2(unsigned long long v, float &a, float &b) {
    unsigned int lo, hi;
    asm("mov.b64 {%0, %1}, %2;" : "=r"(lo), "=r"(hi) : "l"(v));
    a = __uint_as_float(lo); b = __uint_as_float(hi);
}
__device__ __forceinline__ void fma2(unsigned long long &d,
                                     unsigned long long a, unsigned long long b) {
    asm("fma.rn.f32x2 %0, %1, %2, %0;" : "+l"(d) : "l"(a), "l"(b));
}

// ============================================================
// K1: pool(4) + conv(22x13,pad6) + BN  -> g_z[b][o][t]
// grid (2304, 4): blockIdx.y = group of 16 output channels
// ============================================================
__global__ __launch_bounds__(256)
void k_conv(const float* __restrict__ x, const float* __restrict__ cw,
            const float* __restrict__ cb, const float* __restrict__ bg,
            const float* __restrict__ bbv, const float* __restrict__ bm,
            const float* __restrict__ bv)
{
    __shared__ float xp[CH * 264];      // padded pooled input
    __shared__ float ws[16 * 286];      // weights for 16 o's
    __shared__ float sc[16], sh[16];

    int b = blockIdx.x, og = blockIdx.y, tid = threadIdx.x;

    for (int i = tid; i < 16 * 286; i += 256) ws[i] = cw[og * 16 * 286 + i];
    if (tid < 16) {
        int o = og * 16 + tid;
        float inv = bg[o] * rsqrtf(bv[o] + 1e-5f);
        sc[tid] = inv;
        sh[tid] = cb[o] * inv + bbv[o] - bm[o] * inv;
    }
    for (int i = tid; i < CH * 264; i += 256) xp[i] = 0.f;
    __syncthreads();

    const float4* xb = (const float4*)(x + (size_t)b * CH * 1000);
    for (int i = tid; i < CH * TP; i += 256) {
        int c = i / TP, t = i - c * TP;
        float4 v = xb[c * TP + t];
        xp[c * 264 + 6 + t] = 0.25f * (v.x + v.y + v.z + v.w);
    }
    __syncthreads();

    int lo = tid >> 4;              // local o 0..15
    int tg = tid & 15;
    int o = og * 16 + lo;
    float scale = sc[lo], shift = sh[lo];
    const float* wrow = ws + lo * 286;
    float* zrow = g_z + ((size_t)b * ST + o) * TP;

    for (int cs = tg; cs < 25; cs += 16) {
        int t0 = cs * 10;
        unsigned long long acc[5];
        #pragma unroll
        for (int j = 0; j < 5; ++j) acc[j] = 0ull;

        #pragma unroll 1
        for (int c = 0; c < CH; ++c) {
            const float* row = xp + c * 264 + t0;
            float xr[22];
            #pragma unroll
            for (int j = 0; j < 22; ++j) xr[j] = row[j];
            unsigned long long xe[11], xo[10];
            #pragma unroll
            for (int j = 0; j < 11; ++j) xe[j] = pk2(xr[2 * j], xr[2 * j + 1]);
            #pragma unroll
            for (int j = 0; j < 10; ++j) xo[j] = pk2(xr[2 * j + 1], xr[2 * j + 2]);

            const float* wc = wrow + c * KW;
            #pragma unroll
            for (int k = 0; k < KW; ++k) {
                float wv = wc[k];
                unsigned long long w2 = pk2(wv, wv);
                if ((k & 1) == 0) {
                    #pragma unroll
                    for (int j = 0; j < 5; ++j) fma2(acc[j], xe[(k >> 1) + j], w2);
                } else {
                    #pragma unroll
                    for (int j = 0; j < 5; ++j) fma2(acc[j], xo[(k >> 1) + j], w2);
                }
            }
        }
        #pragma unroll
        for (int j = 0; j < 5; ++j) {
            float lov, hiv; upk2(acc[j], lov, hiv);
            zrow[t0 + 2 * j]     = lov * scale + shift;
            zrow[t0 + 2 * j + 1] = hiv * scale + shift;
        }
    }
}

// ============================================================
// K2: per b: 3 blocks -> center, P = W*Zc, y += P P^T / tr
//     y = y/3 + 1e-5 * W W^T  -> g_y
// ============================================================
__global__ __launch_bounds__(256)
void k_covmap(const float* __restrict__ W)
{
    __shared__ float zs[64 * 85];
    __shared__ float ps[32 * 85];
    __shared__ float Wsh[32 * 64];
    __shared__ float yacc[1024];
    __shared__ float red[256];
    __shared__ float smean[64];
    __shared__ float s_rtr;

    int b = blockIdx.x, tid = threadIdx.x;
    for (int i = tid; i < 2048; i += 256) Wsh[i] = W[i];
    for (int i = tid; i < 1024; i += 256) yacc[i] = 0.f;
    __syncthreads();

    const int offs[3] = {0, 84, 167};
    const int lens[3] = {84, 83, 83};

    for (int blk = 0; blk < 3; ++blk) {
        int off = offs[blk], l = lens[blk];
        for (int i = tid; i < 64 * l; i += 256) {
            int c = i / l, t = i - c * l;
            zs[c * 85 + t] = g_z[((size_t)b * 64 + c) * TP + off + t];
        }
        __syncthreads();
        if (tid < 64) {
            float s = 0.f;
            for (int t = 0; t < l; ++t) s += zs[tid * 85 + t];
            smean[tid] = s / (float)l;
        }
        __syncthreads();
        float loc = 0.f;
        for (int i = tid; i < 64 * l; i += 256) {
            int c = i / l, t = i - c * l;
            float v = zs[c * 85 + t] - smean[c];
            zs[c * 85 + t] = v;
            loc += v * v;
        }
        red[tid] = loc; __syncthreads();
        for (int s = 128; s > 0; s >>= 1) {
            if (tid < s) red[tid] += red[tid + s];
            __syncthreads();
        }
        if (tid == 0) s_rtr = 1.f / red[0];
        __syncthreads();

        // P(32 x l) = Wsh(32x64) * zs(64 x l)
        {
            int ty = tid >> 4, tx = tid & 15;
            int o0 = 2 * ty;
            float a0[6] = {0,0,0,0,0,0}, a1[6] = {0,0,0,0,0,0};
            for (int c = 0; c < 64; ++c) {
                float w0 = Wsh[o0 * 64 + c];
                float w1 = Wsh[(o0 + 1) * 64 + c];
                const float* zr = zs + c * 85 + tx;
                #pragma unroll
                for (int j = 0; j < 6; ++j) {
                    int t = tx + 16 * j;
                    if (t < l) {
                        float zv = zr[16 * j];
                        a0[j] += w0 * zv;
                        a1[j] += w1 * zv;
                    }
                }
            }
            #pragma unroll
            for (int j = 0; j < 6; ++j) {
                int t = tx + 16 * j;
                if (t < l) {
                    ps[o0 * 85 + t] = a0[j];
                    ps[(o0 + 1) * 85 + t] = a1[j];
                }
            }
        }
        __syncthreads();

        if (tid < 64) {
            int ti = tid >> 3, tj = tid & 7;
            int o0 = 4 * ti, p0 = 4 * tj;
            float acc[4][4];
            #pragma unroll
            for (int i = 0; i < 4; ++i)
                #pragma unroll
                for (int j = 0; j < 4; ++j) acc[i][j] = 0.f;
            for (int t = 0; t < l; ++t) {
                float u[4], v[4];
                #pragma unroll
                for (int i = 0; i < 4; ++i) u[i] = ps[(o0 + i) * 85 + t];
                #pragma unroll
                for (int j = 0; j < 4; ++j) v[j] = ps[(p0 + j) * 85 + t];
                #pragma unroll
                for (int i = 0; i < 4; ++i)
                    #pragma unroll
                    for (int j = 0; j < 4; ++j) acc[i][j] += u[i] * v[j];
            }
            float rtr = s_rtr;
            #pragma unroll
            for (int i = 0; i < 4; ++i)
                #pragma unroll
                for (int j = 0; j < 4; ++j)
                    yacc[(o0 + i) * 32 + p0 + j] += acc[i][j] * rtr;
        }
        __syncthreads();
    }

    if (tid < 64) {
        int ti = tid >> 3, tj = tid & 7;
        int o0 = 4 * ti, p0 = 4 * tj;
        float acc[4][4];
        #pragma unroll
        for (int i = 0; i < 4; ++i)
            #pragma unroll
            for (int j = 0; j < 4; ++j) acc[i][j] = 0.f;
        for (int c = 0; c < 64; ++c) {
            float u[4], v[4];
            #pragma unroll
            for (int i = 0; i < 4; ++i) u[i] = Wsh[(o0 + i) * 64 + c];
            #pragma unroll
            for (int j = 0; j < 4; ++j) v[j] = Wsh[(p0 + j) * 64 + c];
            #pragma unroll
            for (int i = 0; i < 4; ++i)
                #pragma unroll
                for (int j = 0; j < 4; ++j) acc[i][j] += u[i] * v[j];
        }
        #pragma unroll
        for (int i = 0; i < 4; ++i)
            #pragma unroll
            for (int j = 0; j < 4; ++j)
                g_y[(size_t)b * 1024 + (o0 + i) * 32 + p0 + j] =
                    yacc[(o0 + i) * 32 + p0 + j] * (1.f / 3.f) + 1e-5f * acc[i][j];
    }
}

// ============================================================
// K3: one warp per 32x32 SPD matrix: Hestenes Jacobi eigh,
//     logm = U log(max(lam,1e-4)) U^T, write scaled triu -> fe
// ============================================================
__global__ __launch_bounds__(256)
void k_eig(float* __restrict__ feout)
{
    __shared__ float sm[8 * 1088];   // per warp: Us[32*33] + g[32]

    int tid = threadIdx.x;
    int wid = tid >> 5, lane = tid & 31;
    int b = blockIdx.x * 8 + wid;
    if (b >= BB) return;

    const float* Y = g_y + (size_t)b * 1024;
    float a[32];
    #pragma unroll
    for (int i = 0; i < 32; ++i) a[i] = Y[i * 32 + lane];

    for (int sweep = 0; sweep < 8; ++sweep) {
        for (int r = 0; r < 31; ++r) {
            int partner;
            if (lane == 0) partner = (30 + r) % 31 + 1;
            else {
                int pos = ((lane - 1 - r) % 31 + 31) % 31 + 1;
                int pp = 31 - pos;
                partner = (pp == 0) ? 0 : ((pp - 1 + r) % 31) + 1;
            }
            float oth[32];
            #pragma unroll
            for (int i = 0; i < 32; ++i)
                oth[i] = __shfl_sync(0xffffffffu, a[i], partner);
            float own = 0.f, dot = 0.f;
            #pragma unroll
            for (int i = 0; i < 32; ++i) { own += a[i] * a[i]; dot += a[i] * oth[i]; }
            float othn = __shfl_sync(0xffffffffu, own, partner);
            bool isp = lane < partner;
            float app = isp ? own : othn;
            float aqq = isp ? othn : own;
            float c = 1.f, s = 0.f;
            if (dot * dot > 1e-24f * app * aqq) {
                float zeta = (aqq - app) / (2.f * dot);
                float t = ((zeta >= 0.f) ? 1.f : -1.f) /
                          (fabsf(zeta) + sqrtf(1.f + zeta * zeta));
                c = rsqrtf(1.f + t * t);
                s = c * t;
            }
            #pragma unroll
            for (int i = 0; i < 32; ++i)
                a[i] = isp ? (c * a[i] - s * oth[i]) : (s * oth[i] + c * a[i]);
        }
    }

    float own = 0.f;
    #pragma unroll
    for (int i = 0; i < 32; ++i) own += a[i] * a[i];
    float lam = sqrtf(own);
    float g = logf(fmaxf(lam, 1e-4f));
    float inv = 1.f / lam;

    float* Us = sm + wid * 1088;
    float* gs = Us + 1056;
    #pragma unroll
    for (int i = 0; i < 32; ++i) Us[lane * 33 + i] = a[i] * inv;
    gs[lane] = g;
    __syncwarp();

    float scal[32];
    #pragma unroll
    for (int j = 0; j < 32; ++j) scal[j] = gs[j] * Us[j * 33 + lane];
    float acc[32];
    #pragma unroll
    for (int i = 0; i < 32; ++i) acc[i] = 0.f;
    #pragma unroll
    for (int j = 0; j < 32; ++j) {
        float sj = scal[j];
        #pragma unroll
        for (int i = 0; i < 32; ++i) acc[i] += sj * Us[j * 33 + i];
    }

    // acc[i] = logm[lane][i]; write triu row `lane`
    const float SQ2 = 1.41421356237309515f;
    int bi = 32 * lane - (lane * (lane - 1)) / 2 - lane;  // base - lane
    float* fb = feout + (size_t)b * NFE + bi;
    #pragma unroll
    for (int j = 0; j < 32; ++j) {
        if (j >= lane) fb[j] = acc[j] * ((j == lane) ? 1.f : SQ2);
    }
}

// ============================================================
// K4: logits(256,4) = fe(256,4752) @ Wl(4,4752)^T + bl
// ============================================================
__global__ __launch_bounds__(128)
void k_linear(const float* __restrict__ fe, const float* __restrict__ Wl,
              const float* __restrict__ bl, float* __restrict__ out)
{
    __shared__ float red[128 * 4];
    int bs = blockIdx.x, tid = threadIdx.x;
    const float* fr = fe + (size_t)bs * 4752;
    float acc[4] = {0.f, 0.f, 0.f, 0.f};
    for (int i = tid; i < 4752; i += 128) {
        float v = fr[i];
        #pragma unroll
        for (int c = 0; c < 4; ++c) acc[c] += v * Wl[c * 4752 + i];
    }
    #pragma unroll
    for (int c = 0; c < 4; ++c) red[tid * 4 + c] = acc[c];
    __syncthreads();
    for (int s = 64; s > 0; s >>= 1) {
        if (tid < s) {
            #pragma unroll
            for (int c = 0; c < 4; ++c) red[tid * 4 + c] += red[(tid + s) * 4 + c];
        }
        __syncthreads();
    }
    if (tid < 4) out[bs * 4 + tid] = red[tid] + bl[tid];
}

extern "C" void kernel_launch(void* const* d_in, const int* in_sizes, int n_in,
                              void* d_out, int out_size) {
    const float* x   = (const float*)d_in[0];
    const float* cw  = (const float*)d_in[1];
    const float* cb  = (const float*)d_in[2];
    const float* bg  = (const float*)d_in[3];
    const float* bb  = (const float*)d_in[4];
    const float* bm  = (const float*)d_in[5];
    const float* bv  = (const float*)d_in[6];
    const float* W   = (const float*)d_in[7];
    const float* Wl  = (const float*)d_in[8];
    const float* bl  = (const float*)d_in[9];
    float* fe     = (float*)d_out;
    float* logits = fe + (size_t)BB * NFE;

    k_conv<<<dim3(BB, 4), 256>>>(x, cw, cb, bg, bb, bm, bv);
    k_covmap<<<BB, 256>>>(W);
    k_eig<<<BB / 8, 256>>>(fe);
    k_linear<<<256, 128>>>(fe, Wl, bl, logits);
}